// round 1
// baseline (speedup 1.0000x reference)
#include <cuda_runtime.h>

#define CHUNKS 8
#define TPB 256
#define COLS_PER_BLOCK (TPB * 4)

// Scratch: partial sums [B, CHUNKS, D]. 16 MB static, well above the
// 16*8*4096 floats (2 MB) this problem needs.
__device__ float g_partial[1 << 22];

// ---------------------------------------------------------------------------
// Kernel 1: per-(sequence, token-chunk, column-slice) partial sums.
// Streams only the unmasked rows; fully coalesced float4 loads.
// ---------------------------------------------------------------------------
__global__ void __launch_bounds__(TPB) pool_partial_kernel(
    const float* __restrict__ hs,
    const int* __restrict__ plens,
    const int* __restrict__ ilens,
    int D)
{
    const int b     = blockIdx.x;
    const int chunk = blockIdx.y;
    const int dblk  = blockIdx.z;

    // Segment start: tiny prefix sum (B <= 16); reads hit L2/L1 after first block.
    long start = 0;
    for (int i = 0; i < b; ++i) start += plens[i];

    const int pl = plens[b];
    const int il = ilens[b];
    const int n  = pl - il;  // valid token count

    const int t0 = (int)((long)chunk * n / CHUNKS);
    const int t1 = (int)((long)(chunk + 1) * n / CHUNKS);

    const int col = dblk * COLS_PER_BLOCK + threadIdx.x * 4;
    if (col >= D) return;

    const float* base = hs + (start + il) * (long)D + col;

    float4 acc = make_float4(0.f, 0.f, 0.f, 0.f);

    int t = t0;
    // Unroll by 4 with independent loads for MLP.
    for (; t + 4 <= t1; t += 4) {
        float4 v0 = *(const float4*)(base + (long)(t + 0) * D);
        float4 v1 = *(const float4*)(base + (long)(t + 1) * D);
        float4 v2 = *(const float4*)(base + (long)(t + 2) * D);
        float4 v3 = *(const float4*)(base + (long)(t + 3) * D);
        acc.x += v0.x + v1.x + v2.x + v3.x;
        acc.y += v0.y + v1.y + v2.y + v3.y;
        acc.z += v0.z + v1.z + v2.z + v3.z;
        acc.w += v0.w + v1.w + v2.w + v3.w;
    }
    for (; t < t1; ++t) {
        float4 v = *(const float4*)(base + (long)t * D);
        acc.x += v.x; acc.y += v.y; acc.z += v.z; acc.w += v.w;
    }

    float* out = g_partial + ((long)b * CHUNKS + chunk) * D + col;
    *(float4*)out = acc;
}

// ---------------------------------------------------------------------------
// Kernel 2: reduce chunks -> mean, L2-normalize per sequence.
// One block per sequence, 1024 threads. Mean kept in registers.
// ---------------------------------------------------------------------------
#define FTPB 1024
#define MAX_VECS_PER_THREAD 8   // supports D up to 32768

__global__ void __launch_bounds__(FTPB) pool_finalize_kernel(
    const int* __restrict__ plens,
    const int* __restrict__ ilens,
    float* __restrict__ out,
    int D)
{
    const int b   = blockIdx.x;
    const int cnt = plens[b] - ilens[b];
    const float inv = 1.0f / (float)cnt;

    float4 mloc[MAX_VECS_PER_THREAD];
    int    cloc[MAX_VECS_PER_THREAD];
    int nv = 0;

    float ss = 0.f;
    for (int col = threadIdx.x * 4; col < D; col += FTPB * 4) {
        float4 a = make_float4(0.f, 0.f, 0.f, 0.f);
        const float* p = g_partial + (long)b * CHUNKS * D + col;
        #pragma unroll
        for (int c = 0; c < CHUNKS; ++c) {
            float4 v = *(const float4*)(p + (long)c * D);
            a.x += v.x; a.y += v.y; a.z += v.z; a.w += v.w;
        }
        a.x *= inv; a.y *= inv; a.z *= inv; a.w *= inv;
        ss += a.x * a.x + a.y * a.y + a.z * a.z + a.w * a.w;
        if (nv < MAX_VECS_PER_THREAD) { mloc[nv] = a; cloc[nv] = col; ++nv; }
    }

    // Block reduction of ss.
    __shared__ float red[32];
    __shared__ float s_rnorm;
    unsigned mask = 0xFFFFFFFFu;
    #pragma unroll
    for (int off = 16; off > 0; off >>= 1)
        ss += __shfl_xor_sync(mask, ss, off);
    const int lane = threadIdx.x & 31;
    const int wid  = threadIdx.x >> 5;
    if (lane == 0) red[wid] = ss;
    __syncthreads();
    if (wid == 0) {
        float v = (lane < (FTPB / 32)) ? red[lane] : 0.f;
        #pragma unroll
        for (int off = 16; off > 0; off >>= 1)
            v += __shfl_xor_sync(mask, v, off);
        if (lane == 0) {
            float norm = sqrtf(v);
            norm = fmaxf(norm, 1e-12f);
            s_rnorm = 1.0f / norm;
        }
    }
    __syncthreads();
    const float r = s_rnorm;

    float* ob = out + (long)b * D;
    for (int i = 0; i < nv; ++i) {
        float4 a = mloc[i];
        a.x *= r; a.y *= r; a.z *= r; a.w *= r;
        *(float4*)(ob + cloc[i]) = a;
    }
}

// ---------------------------------------------------------------------------
extern "C" void kernel_launch(void* const* d_in, const int* in_sizes, int n_in,
                              void* d_out, int out_size)
{
    const float* hs    = (const float*)d_in[0];
    const int*   plens = (const int*)d_in[1];
    const int*   ilens = (const int*)d_in[2];
    float*       out   = (float*)d_out;

    const int B = in_sizes[1];
    const int D = out_size / B;

    const int dblocks = (D + COLS_PER_BLOCK - 1) / COLS_PER_BLOCK;

    dim3 grid1(B, CHUNKS, dblocks);
    pool_partial_kernel<<<grid1, TPB>>>(hs, plens, ilens, D);

    pool_finalize_kernel<<<B, FTPB>>>(plens, ilens, out, D);
}

// round 2
// speedup vs baseline: 1.0246x; 1.0246x over previous
#include <cuda_runtime.h>

#define CHUNKS 8
#define TPB 256
#define COLS_PER_BLOCK (TPB * 4)

// Scratch: partial sums [B, CHUNKS, D].
__device__ float g_partial[1 << 22];

// ---------------------------------------------------------------------------
// Kernel 1: per-(sequence, token-chunk, column-slice) partial sums.
// Streams only unmasked rows; coalesced float4 loads, 8-deep MLP, L2-streaming.
// ---------------------------------------------------------------------------
__global__ void __launch_bounds__(TPB) pool_partial_kernel(
    const float* __restrict__ hs,
    const int* __restrict__ plens,
    const int* __restrict__ ilens,
    int D)
{
    const int b     = blockIdx.x;
    const int chunk = blockIdx.y;
    const int dblk  = blockIdx.z;

    long start = 0;
    for (int i = 0; i < b; ++i) start += plens[i];

    const int pl = plens[b];
    const int il = ilens[b];
    const int n  = pl - il;  // valid token count

    const int t0 = (int)((long)chunk * n / CHUNKS);
    const int t1 = (int)((long)(chunk + 1) * n / CHUNKS);

    const int col = dblk * COLS_PER_BLOCK + threadIdx.x * 4;
    if (col >= D) return;

    const float* base = hs + (start + il) * (long)D + col;

    float4 acc0 = make_float4(0.f, 0.f, 0.f, 0.f);
    float4 acc1 = make_float4(0.f, 0.f, 0.f, 0.f);

    int t = t0;
    // Unroll by 8 with independent streaming loads for deep MLP.
    for (; t + 8 <= t1; t += 8) {
        float4 v0 = __ldcs((const float4*)(base + (long)(t + 0) * D));
        float4 v1 = __ldcs((const float4*)(base + (long)(t + 1) * D));
        float4 v2 = __ldcs((const float4*)(base + (long)(t + 2) * D));
        float4 v3 = __ldcs((const float4*)(base + (long)(t + 3) * D));
        float4 v4 = __ldcs((const float4*)(base + (long)(t + 4) * D));
        float4 v5 = __ldcs((const float4*)(base + (long)(t + 5) * D));
        float4 v6 = __ldcs((const float4*)(base + (long)(t + 6) * D));
        float4 v7 = __ldcs((const float4*)(base + (long)(t + 7) * D));
        acc0.x += (v0.x + v1.x) + (v2.x + v3.x);
        acc0.y += (v0.y + v1.y) + (v2.y + v3.y);
        acc0.z += (v0.z + v1.z) + (v2.z + v3.z);
        acc0.w += (v0.w + v1.w) + (v2.w + v3.w);
        acc1.x += (v4.x + v5.x) + (v6.x + v7.x);
        acc1.y += (v4.y + v5.y) + (v6.y + v7.y);
        acc1.z += (v4.z + v5.z) + (v6.z + v7.z);
        acc1.w += (v4.w + v5.w) + (v6.w + v7.w);
    }
    for (; t < t1; ++t) {
        float4 v = __ldcs((const float4*)(base + (long)t * D));
        acc0.x += v.x; acc0.y += v.y; acc0.z += v.z; acc0.w += v.w;
    }
    acc0.x += acc1.x; acc0.y += acc1.y; acc0.z += acc1.z; acc0.w += acc1.w;

    float* out = g_partial + ((long)b * CHUNKS + chunk) * D + col;
    *(float4*)out = acc0;
}

// ---------------------------------------------------------------------------
// Kernel 2: reduce chunks -> mean, L2-normalize per sequence.
// One block per sequence, 512 threads, 2 float4 columns per thread (16
// independent loads in flight per thread).
// ---------------------------------------------------------------------------
#define FTPB 512
#define MAX_VECS_PER_THREAD 16   // supports D up to 32768

__global__ void __launch_bounds__(FTPB) pool_finalize_kernel(
    const int* __restrict__ plens,
    const int* __restrict__ ilens,
    float* __restrict__ out,
    int D)
{
    const int b   = blockIdx.x;
    const int cnt = plens[b] - ilens[b];
    const float inv = 1.0f / (float)cnt;

    float4 mloc[MAX_VECS_PER_THREAD];
    int    cloc[MAX_VECS_PER_THREAD];
    int nv = 0;

    const float* pb = g_partial + (long)b * CHUNKS * D;

    float ss = 0.f;
    // Process two column-float4s per outer iteration for ILP.
    for (int col = threadIdx.x * 4; col < D; col += FTPB * 4 * 2) {
        const int col2 = col + FTPB * 4;
        float4 a = make_float4(0.f, 0.f, 0.f, 0.f);
        float4 c = make_float4(0.f, 0.f, 0.f, 0.f);
        const bool has2 = (col2 < D);
        #pragma unroll
        for (int ch = 0; ch < CHUNKS; ++ch) {
            float4 v = __ldg((const float4*)(pb + (long)ch * D + col));
            a.x += v.x; a.y += v.y; a.z += v.z; a.w += v.w;
            if (has2) {
                float4 w = __ldg((const float4*)(pb + (long)ch * D + col2));
                c.x += w.x; c.y += w.y; c.z += w.z; c.w += w.w;
            }
        }
        a.x *= inv; a.y *= inv; a.z *= inv; a.w *= inv;
        ss += a.x * a.x + a.y * a.y + a.z * a.z + a.w * a.w;
        if (nv < MAX_VECS_PER_THREAD) { mloc[nv] = a; cloc[nv] = col; ++nv; }
        if (has2) {
            c.x *= inv; c.y *= inv; c.z *= inv; c.w *= inv;
            ss += c.x * c.x + c.y * c.y + c.z * c.z + c.w * c.w;
            if (nv < MAX_VECS_PER_THREAD) { mloc[nv] = c; cloc[nv] = col2; ++nv; }
        }
    }

    // Block reduction of ss.
    __shared__ float red[FTPB / 32];
    __shared__ float s_rnorm;
    unsigned mask = 0xFFFFFFFFu;
    #pragma unroll
    for (int off = 16; off > 0; off >>= 1)
        ss += __shfl_xor_sync(mask, ss, off);
    const int lane = threadIdx.x & 31;
    const int wid  = threadIdx.x >> 5;
    if (lane == 0) red[wid] = ss;
    __syncthreads();
    if (wid == 0) {
        float v = (lane < (FTPB / 32)) ? red[lane] : 0.f;
        #pragma unroll
        for (int off = 16; off > 0; off >>= 1)
            v += __shfl_xor_sync(mask, v, off);
        if (lane == 0) {
            float norm = sqrtf(v);
            norm = fmaxf(norm, 1e-12f);
            s_rnorm = 1.0f / norm;
        }
    }
    __syncthreads();
    const float r = s_rnorm;

    float* ob = out + (long)b * D;
    #pragma unroll 4
    for (int i = 0; i < nv; ++i) {
        float4 a = mloc[i];
        a.x *= r; a.y *= r; a.z *= r; a.w *= r;
        *(float4*)(ob + cloc[i]) = a;
    }
}

// ---------------------------------------------------------------------------
extern "C" void kernel_launch(void* const* d_in, const int* in_sizes, int n_in,
                              void* d_out, int out_size)
{
    const float* hs    = (const float*)d_in[0];
    const int*   plens = (const int*)d_in[1];
    const int*   ilens = (const int*)d_in[2];
    float*       out   = (float*)d_out;

    const int B = in_sizes[1];
    const int D = out_size / B;

    const int dblocks = (D + COLS_PER_BLOCK - 1) / COLS_PER_BLOCK;

    dim3 grid1(B, CHUNKS, dblocks);
    pool_partial_kernel<<<grid1, TPB>>>(hs, plens, ilens, D);

    pool_finalize_kernel<<<B, FTPB>>>(plens, ilens, out, D);
}